// round 15
// baseline (speedup 1.0000x reference)
#include <cuda_runtime.h>
#include <math.h>
#include <stdint.h>

#define U     256
#define SZ    65536          // U*U
#define BATCH 32768
#define NL    6
#define DIN   784
#define DOUT  10
#define NB    32             // panel width
#define NSTEP (U / NB)       // 8 block steps
#define NCTA  96             // mega-kernel grid (<=148 SMs -> co-resident)

// ===================== device-global scratch (no runtime allocs) =====================
__device__ float g_M   [NL][SZ];          // GENP inverse; later reused as tree bufs
__device__ float g_M2  [NL][SZ];          // Newton-refined inverse
__device__ float g_R   [NL][SZ];          // Newton residual
__device__ float g_MTn [NL][SZ];          // -(M2)^T
__device__ float g_Mul8[NSTEP][NL][NB * U]; // multipliers, per-step buffers, [p][r]
__device__ float g_ipiv[NL][U];           // 1/pivot per global step
__device__ unsigned int g_flagw[NL][NSTEP];
__device__ float g_c   [U];               // final constant c0
__device__ float g_G   [DOUT * U];
__device__ float g_F   [DIN * DOUT];
__device__ float g_f   [16];
__device__ float g_sink[NCTA];            // prefetch DCE sink
__device__ unsigned int g_barcnt = 0;     // grid barrier state
__device__ unsigned int g_bargen = 0;

// =====================================================================
// device-wide barrier (proven round-13 pattern)
// =====================================================================
__device__ __forceinline__ void grid_sync() {
    __syncthreads();
    if (threadIdx.x == 0) {
        __threadfence();
        const unsigned int gen = atomicAdd(&g_bargen, 0u);
        if (atomicAdd(&g_barcnt, 1u) == NCTA - 1) {
            g_barcnt = 0;
            __threadfence();
            atomicAdd(&g_bargen, 1u);
        } else {
            while (atomicAdd(&g_bargen, 0u) == gen) { }
        }
    }
    __syncthreads();
}

// =====================================================================
// inversion body (proven round-12/13 arithmetic), CTA = (tile jt, layer l)
// =====================================================================
__device__ void invert_body(const float* __restrict__ B0, int l, int jt,
                            float (*sp)[NB], float* sipv) {
    const int r = threadIdx.x;
    const float* A = B0 + (size_t)l * SZ;
    const int j0 = jt * NB;

    float t[NB];
    #pragma unroll
    for (int c = 0; c < NB; c += 4)
        *(float4*)&t[c] = *(const float4*)&A[r * U + j0 + c];

    #pragma unroll 1
    for (int kb = 0; kb < NSTEP; kb++) {
        float* Mul = &g_Mul8[kb][l][0];
        const int c0g = kb * NB;
        if (jt == kb) {
            if (r == c0g) {
                Mul[0 * U + r] = t[0];
                const float ip = 1.0f / t[0];
                g_ipiv[l][c0g] = ip;
                #pragma unroll
                for (int c = 0; c < NB; c++) t[c] = (c == 0) ? ip : t[c] * ip;
                #pragma unroll
                for (int c = 0; c < NB; c++) sp[0][c] = t[c];
            }
            #pragma unroll
            for (int p = 0; p < NB; p++) {
                __syncthreads();
                const int gp = c0g + p;
                if (r != gp) {
                    const float f = t[p];
                    Mul[p * U + r] = f;
                    const float ip = sp[p & 1][p];
                    #pragma unroll
                    for (int c = 0; c < NB; c += 4) {
                        float4 s4 = *(const float4*)&sp[p & 1][c];
                        t[c + 0] -= f * s4.x; t[c + 1] -= f * s4.y;
                        t[c + 2] -= f * s4.z; t[c + 3] -= f * s4.w;
                    }
                    t[p] = -f * ip;
                    if (p + 1 < NB && r == gp + 1) {
                        Mul[(p + 1) * U + r] = t[p + 1];
                        const float ip2 = 1.0f / t[p + 1];
                        g_ipiv[l][gp + 1] = ip2;
                        #pragma unroll
                        for (int c = 0; c < NB; c++)
                            t[c] = (c == p + 1) ? ip2 : t[c] * ip2;
                        #pragma unroll
                        for (int c = 0; c < NB; c++) sp[(p + 1) & 1][c] = t[c];
                    }
                }
            }
            __threadfence();
            __syncthreads();
            if (r == 0) atomicExch(&g_flagw[l][kb], 1u);
        } else {
            if (r == 0) {
                while (atomicAdd(&g_flagw[l][kb], 0u) == 0u) { }
            }
            __syncthreads();
            float m[NB];
            #pragma unroll
            for (int p = 0; p < NB; p++) m[p] = Mul[p * U + r];
            if (r < NB) sipv[r] = g_ipiv[l][c0g + r];
            __syncthreads();
            if (r == c0g) {
                const float ip = sipv[0];
                #pragma unroll
                for (int c = 0; c < NB; c++) { t[c] *= ip; sp[0][c] = t[c]; }
            }
            #pragma unroll
            for (int p = 0; p < NB; p++) {
                __syncthreads();
                const int gp = c0g + p;
                if (r != gp) {
                    const float f = m[p];
                    #pragma unroll
                    for (int c = 0; c < NB; c += 4) {
                        float4 s4 = *(const float4*)&sp[p & 1][c];
                        t[c + 0] -= f * s4.x; t[c + 1] -= f * s4.y;
                        t[c + 2] -= f * s4.z; t[c + 3] -= f * s4.w;
                    }
                    if (p + 1 < NB && r == gp + 1) {
                        const float ip2 = sipv[p + 1];
                        #pragma unroll
                        for (int c = 0; c < NB; c++) { t[c] *= ip2; sp[(p + 1) & 1][c] = t[c]; }
                    }
                }
            }
        }
    }

    #pragma unroll
    for (int c = 0; c < NB; c += 4)
        *(float4*)&g_M[l][r * U + j0 + c] = *(float4*)&t[c];
}

// =====================================================================
// x prefetch into L2 (idle CTAs during inversion). Reads every float4
// of x once; sum sunk to g_sink to defeat DCE.
// =====================================================================
__device__ void prefetch_x(const float* __restrict__ x, int slot) {
    const size_t total4 = (size_t)BATCH * DIN / 4;   // 6,422,528 float4
    const size_t stride = (size_t)(NCTA - 48) * 256;
    float acc = 0.0f;
    for (size_t i = (size_t)slot * 256 + threadIdx.x; i < total4; i += stride) {
        float4 v = ((const float4*)x)[i];
        acc += v.x + v.y + v.z + v.w;
    }
    // warp-reduce then one store per CTA (deterministic)
    #pragma unroll
    for (int o = 16; o > 0; o >>= 1)
        acc += __shfl_down_sync(0xFFFFFFFFu, acc, o);
    if (threadIdx.x == 0) g_sink[48 + slot] = acc;
}

// =====================================================================
// 64x64x256 GEMM tile body (proven round-13)
//   mode 0: C = A*B   mode 1: C = 2I - A*B
//   mode 2: C = A*B, plus transposed-negated store to T
// =====================================================================
__device__ void gemm_tile(float* shbuf,
                          const float* __restrict__ A, const float* __restrict__ Bm,
                          float* __restrict__ C, float* __restrict__ T,
                          int mode, int bx, int by) {
    float (*As)[68] = (float(*)[68])shbuf;
    float (*Bs)[68] = (float(*)[68])(shbuf + 32 * 68);
    const int tid = threadIdx.x;
    const int i0 = by * 64, j0 = bx * 64;
    const int rf = (tid >> 4) * 4, cf = (tid & 15) * 4;
    float acc[4][4];
    #pragma unroll
    for (int r = 0; r < 4; r++)
        #pragma unroll
        for (int c = 0; c < 4; c++) acc[r][c] = 0.0f;

    for (int k0 = 0; k0 < U; k0 += 32) {
        #pragma unroll
        for (int m = 0; m < 2; m++) {
            int s = tid + m * 256;
            int ii = s >> 3, kc = (s & 7) * 4;
            float4 a = *(const float4*)&A[(i0 + ii) * U + k0 + kc];
            As[kc + 0][ii] = a.x; As[kc + 1][ii] = a.y;
            As[kc + 2][ii] = a.z; As[kc + 3][ii] = a.w;
            int kk = s >> 4, jc = (s & 15) * 4;
            *(float4*)&Bs[kk][jc] = *(const float4*)&Bm[(k0 + kk) * U + j0 + jc];
        }
        __syncthreads();
        #pragma unroll
        for (int kk = 0; kk < 32; kk++) {
            float4 a4 = *(const float4*)&As[kk][rf];
            float4 b4 = *(const float4*)&Bs[kk][cf];
            float av[4] = {a4.x, a4.y, a4.z, a4.w};
            float bv[4] = {b4.x, b4.y, b4.z, b4.w};
            #pragma unroll
            for (int r = 0; r < 4; r++)
                #pragma unroll
                for (int c = 0; c < 4; c++) acc[r][c] += av[r] * bv[c];
        }
        __syncthreads();
    }
    if (mode == 2) {
        #pragma unroll
        for (int r = 0; r < 4; r++) {
            const int i = i0 + rf + r;
            *(float4*)&C[i * U + j0 + cf] =
                make_float4(acc[r][0], acc[r][1], acc[r][2], acc[r][3]);
        }
        #pragma unroll
        for (int c = 0; c < 4; c++) {
            const int j = j0 + cf + c;
            *(float4*)&T[j * U + i0 + rf] =
                make_float4(-acc[0][c], -acc[1][c], -acc[2][c], -acc[3][c]);
        }
    } else {
        #pragma unroll
        for (int r = 0; r < 4; r++) {
            int i = i0 + rf + r;
            #pragma unroll
            for (int c = 0; c < 4; c++) {
                int j = j0 + cf + c;
                float v = acc[r][c];
                if (mode == 1) v = ((i == j) ? 2.0f : 0.0f) - v;
                C[i * U + j] = v;
            }
        }
    }
}

// =====================================================================
// constant-chain layers [l0,l1): c0' = MTn_l*c1 ; c1' = M2_l*(c0+q_l)
// (proven round-13; state persists in CTA95's smem)
// =====================================================================
__device__ void const_layers(int l0, int l1, const float* __restrict__ q,
                             float* c0s, float* c1s, float* rq) {
    const int n = threadIdx.x;
    for (int l = l0; l < l1; l++) {
        __syncthreads();
        rq[n] = c0s[n] + q[l * U + n];
        __syncthreads();
        const float* A0 = &g_MTn[l][0];
        const float* A1 = &g_M2[l][0];
        float acc0 = 0.0f, acc1 = 0.0f;
        for (int m = 0; m < U; m += 4) {
            float4 a4 = *(const float4*)&A0[n * U + m];
            acc0 += a4.x * c1s[m];     acc0 += a4.y * c1s[m + 1];
            acc0 += a4.z * c1s[m + 2]; acc0 += a4.w * c1s[m + 3];
            float4 b4 = *(const float4*)&A1[n * U + m];
            acc1 += b4.x * rq[m];      acc1 += b4.y * rq[m + 1];
            acc1 += b4.z * rq[m + 2];  acc1 += b4.w * rq[m + 3];
        }
        __syncthreads();
        c0s[n] = acc0; c1s[n] = acc1;
    }
}

// =====================================================================
// foldG (proven round-13)
// =====================================================================
__device__ void foldG_body(float* shbuf, const float* __restrict__ Wout,
                           const float* __restrict__ K, const float* __restrict__ c0,
                           const float* __restrict__ bin, const float* __restrict__ bout) {
    float* Ws = shbuf;
    float* Gs = shbuf + U * DOUT;
    const int m = threadIdx.x;
    for (int e = m; e < U * DOUT; e += 256) Ws[e] = Wout[e];
    __syncthreads();
    float acc[DOUT];
    #pragma unroll
    for (int d = 0; d < DOUT; d++) acc[d] = 0.0f;
    for (int n = 0; n < U; n++) {
        const float xv = K[n * U + m];
        #pragma unroll
        for (int d = 0; d < DOUT; d++) acc[d] += Ws[n * DOUT + d] * xv;
    }
    #pragma unroll
    for (int d = 0; d < DOUT; d++) { g_G[d * U + m] = acc[d]; Gs[d * U + m] = acc[d]; }
    __syncthreads();
    if (m < DOUT) {
        float f = bout[m];
        for (int e = 0; e < U; e++) f += Gs[m * U + e] * bin[e];
        for (int n = 0; n < U; n++) f += Ws[n * DOUT + m] * c0[n];
        g_f[m] = f;
    }
}

// =====================================================================
// foldF (proven round-13)
// =====================================================================
__device__ void foldF_body(float* shbuf, const float* __restrict__ Win, int blk) {
    float* Gs = shbuf;
    const int tid = threadIdx.x;
    for (int e = tid; e < DOUT * U; e += 256) Gs[e] = g_G[e];
    __syncthreads();
    const int k = blk * 256 + tid;
    if (k >= DIN) return;
    float acc[DOUT];
    #pragma unroll
    for (int d = 0; d < DOUT; d++) acc[d] = 0.0f;
    for (int m = 0; m < U; m++) {
        const float w = Win[(size_t)k * U + m];
        #pragma unroll
        for (int d = 0; d < DOUT; d++) acc[d] += Gs[d * U + m] * w;
    }
    #pragma unroll
    for (int d = 0; d < DOUT; d++) g_F[k * DOUT + d] = acc[d];
}

// =====================================================================
// final x-pass (phase): one row per thread, F smem-resident (stride 12),
// x served from L2 (prefetched during inversion). 2 row-iterations.
// =====================================================================
__device__ void final_body(float* Fs, float* fsv,
                           const float* __restrict__ x, float* __restrict__ out) {
    const int tid = threadIdx.x;
    for (int e = tid; e < DIN * DOUT; e += 256) {
        const int k = e / DOUT, d = e - k * DOUT;
        Fs[k * 12 + d] = g_F[e];
    }
    if (tid < DOUT) fsv[tid] = g_f[tid];
    __syncthreads();

    for (int it = 0; it < 2; it++) {
        const int j = it * (NCTA * 256) + (int)blockIdx.x * 256 + tid;
        if (j >= BATCH) return;
        const float* xr = x + (size_t)j * DIN;
        float acc[DOUT];
        #pragma unroll
        for (int d = 0; d < DOUT; d++) acc[d] = fsv[d];

        for (int k = 0; k < DIN; k += 8) {
            float4 xa = *(const float4*)&xr[k];
            float4 xb = *(const float4*)&xr[k + 4];
            float xk[8] = {xa.x, xa.y, xa.z, xa.w, xb.x, xb.y, xb.z, xb.w};
            #pragma unroll
            for (int kk = 0; kk < 8; kk++) {
                const float xv = xk[kk];
                const float* Fp = &Fs[(k + kk) * 12];
                float4 f0 = *(const float4*)&Fp[0];
                float4 f1 = *(const float4*)&Fp[4];
                float2 f2 = *(const float2*)&Fp[8];
                acc[0] += xv * f0.x; acc[1] += xv * f0.y;
                acc[2] += xv * f0.z; acc[3] += xv * f0.w;
                acc[4] += xv * f1.x; acc[5] += xv * f1.y;
                acc[6] += xv * f1.z; acc[7] += xv * f1.w;
                acc[8] += xv * f2.x; acc[9] += xv * f2.y;
            }
        }
        #pragma unroll
        for (int d = 0; d < DOUT; d++) out[(size_t)j * DOUT + d] = acc[d];
    }
}

// =====================================================================
// THE mega kernel: everything in ONE launch (round-13 structure + P9)
// =====================================================================
__global__ __launch_bounds__(256) void mega_kernel(const float* __restrict__ B0,
                                                   const float* __restrict__ q,
                                                   const float* __restrict__ Wout,
                                                   const float* __restrict__ bin,
                                                   const float* __restrict__ bout,
                                                   const float* __restrict__ Win,
                                                   const float* __restrict__ x,
                                                   float* __restrict__ out) {
    __shared__ __align__(16) float shbuf[9420];   // gemm / folds / Fs(stride12)
    __shared__ __align__(16) float sp[2][NB];
    __shared__ float sipv[NB];
    __shared__ float c0s[U], c1s[U], rq[U];
    __shared__ float fsv[16];
    const int cta = blockIdx.x;
    const int tid = threadIdx.x;

    // P0: reset inversion flags
    if (cta == 0 && tid < NL * NSTEP) ((unsigned int*)g_flagw)[tid] = 0u;
    grid_sync();

    // P1: flag-synced GENP inversion (48 CTAs); others prefetch x into L2
    if (cta < 48) invert_body(B0, cta >> 3, cta & 7, sp, sipv);
    else          prefetch_x(x, cta - 48);
    grid_sync();

    // P2: R = 2I - B0*M   (96 tiles)
    {
        const int l = cta >> 4, t = cta & 15;
        gemm_tile(shbuf, B0 + (size_t)l * SZ, g_M[l], g_R[l], nullptr, 1, t & 3, t >> 2);
    }
    grid_sync();

    // P3: M2 = M*R with fused MTn = -M2^T   (96 tiles)
    {
        const int l = cta >> 4, t = cta & 15;
        gemm_tile(shbuf, g_M[l], g_R[l], g_M2[l], g_MTn[l], 2, t & 3, t >> 2);
    }
    grid_sync();

    // P4: T_z = MTn[2z+1]*M2[2z] -> g_M[z]  (48 tiles);  CTA95: const 0-1
    if (cta < 48) {
        const int z = cta >> 4, t = cta & 15;
        gemm_tile(shbuf, g_MTn[2 * z + 1], g_M2[2 * z], g_M[z], nullptr, 0, t & 3, t >> 2);
    } else if (cta == NCTA - 1) {
        c0s[tid] = 0.0f; c1s[tid] = 0.0f;
        const_layers(0, 2, q, c0s, c1s, rq);
    }
    grid_sync();

    // P5: TT = T1*T0 -> g_M[3]  (16 tiles);  CTA95: const 2-3
    if (cta < 16) gemm_tile(shbuf, g_M[1], g_M[0], g_M[3], nullptr, 0, cta & 3, cta >> 2);
    else if (cta == NCTA - 1) const_layers(2, 4, q, c0s, c1s, rq);
    grid_sync();

    // P6: K = T2*TT -> g_M[4]  (16 tiles);  CTA95: const 4-5 + publish c0
    if (cta < 16) gemm_tile(shbuf, g_M[2], g_M[3], g_M[4], nullptr, 0, cta & 3, cta >> 2);
    else if (cta == NCTA - 1) {
        const_layers(4, 6, q, c0s, c1s, rq);
        g_c[tid] = c0s[tid];
    }
    grid_sync();

    // P7: foldG (CTA 0)
    if (cta == 0) foldG_body(shbuf, Wout, g_M[4], g_c, bin, bout);
    grid_sync();

    // P8: foldF (CTAs 0-3)
    if (cta < 4) foldF_body(shbuf, Win, cta);
    grid_sync();

    // P9: final x-pass (all CTAs, x L2-resident)
    final_body(shbuf, fsv, x, out);
}

// =====================================================================
// launch  (1 launch total)
// =====================================================================
extern "C" void kernel_launch(void* const* d_in, const int* in_sizes, int n_in,
                              void* d_out, int out_size) {
    const float* x    = (const float*)d_in[0];
    const float* Win  = (const float*)d_in[1];
    const float* bin  = (const float*)d_in[2];
    const float* B0   = (const float*)d_in[3];
    const float* q    = (const float*)d_in[4];
    const float* Wout = (const float*)d_in[5];
    const float* bout = (const float*)d_in[6];
    float* out = (float*)d_out;

    mega_kernel<<<NCTA, 256>>>(B0, q, Wout, bin, bout, Win, x, out);
}

// round 16
// speedup vs baseline: 1.1426x; 1.1426x over previous
#include <cuda_runtime.h>
#include <math.h>
#include <stdint.h>

#define U     256
#define SZ    65536          // U*U
#define BATCH 32768
#define NL    6
#define DIN   784
#define DOUT  10
#define NB    32             // panel width
#define NSTEP (U / NB)       // 8 block steps
#define NCTA  96             // mega-kernel grid (<=148 SMs -> co-resident)

// ===================== device-global scratch (no runtime allocs) =====================
__device__ float g_M   [NL][SZ];          // GENP inverse; later reused as tree bufs
__device__ float g_M2  [NL][SZ];          // Newton-refined inverse
__device__ float g_R   [NL][SZ];          // Newton residual
__device__ float g_MTn [NL][SZ];          // -(M2)^T
__device__ float g_Mul8[NSTEP][NL][NB * U]; // multipliers, per-step buffers, [p][r]
__device__ float g_ipiv[NL][U];           // 1/pivot per global step
__device__ unsigned int g_flagw[NL][NSTEP];
__device__ float g_c   [U];               // final constant c0
__device__ float g_G   [DOUT * U];
__device__ float g_F   [DIN * DOUT];
__device__ float g_f   [16];
__device__ unsigned int g_barcnt = 0;     // grid barrier state
__device__ unsigned int g_bargen = 0;

// =====================================================================
// device-wide barrier (proven round-13 pattern)
// =====================================================================
__device__ __forceinline__ void grid_sync() {
    __syncthreads();
    if (threadIdx.x == 0) {
        __threadfence();
        const unsigned int gen = atomicAdd(&g_bargen, 0u);
        if (atomicAdd(&g_barcnt, 1u) == NCTA - 1) {
            g_barcnt = 0;
            __threadfence();
            atomicAdd(&g_bargen, 1u);
        } else {
            while (atomicAdd(&g_bargen, 0u) == gen) { }
        }
    }
    __syncthreads();
}

// =====================================================================
// inversion body: round-12/13 arithmetic, with multiplier/ipiv stores
// BATCHED into registers and dumped once per panel step (values and
// replay-visible data identical; only store timing moves off the chain).
// =====================================================================
__device__ void invert_body(const float* __restrict__ B0, int l, int jt,
                            float (*sp)[NB], float* sipv) {
    const int r = threadIdx.x;
    const float* A = B0 + (size_t)l * SZ;
    const int j0 = jt * NB;

    float t[NB];
    #pragma unroll
    for (int c = 0; c < NB; c += 4)
        *(float4*)&t[c] = *(const float4*)&A[r * U + j0 + c];

    float msave[NB];
    float ipreg = 0.0f;

    #pragma unroll 1
    for (int kb = 0; kb < NSTEP; kb++) {
        float* Mul = &g_Mul8[kb][l][0];
        const int c0g = kb * NB;
        if (jt == kb) {
            // ---- pre-loop pivot prep (step 0) ----
            if (r == c0g) {
                msave[0] = t[0];
                ipreg = 1.0f / t[0];
                #pragma unroll
                for (int c = 0; c < NB; c++) t[c] = (c == 0) ? ipreg : t[c] * ipreg;
                #pragma unroll
                for (int c = 0; c < NB; c++) sp[0][c] = t[c];
            }
            #pragma unroll
            for (int p = 0; p < NB; p++) {
                __syncthreads();
                const int gp = c0g + p;
                if (r != gp) {
                    const float f = t[p];
                    msave[p] = f;
                    const float ip = sp[p & 1][p];
                    #pragma unroll
                    for (int c = 0; c < NB; c += 4) {
                        float4 s4 = *(const float4*)&sp[p & 1][c];
                        t[c + 0] -= f * s4.x; t[c + 1] -= f * s4.y;
                        t[c + 2] -= f * s4.z; t[c + 3] -= f * s4.w;
                    }
                    t[p] = -f * ip;
                    if (p + 1 < NB && r == gp + 1) {
                        msave[p + 1] = t[p + 1];
                        const float ip2 = 1.0f / t[p + 1];
                        ipreg = ip2;
                        #pragma unroll
                        for (int c = 0; c < NB; c++)
                            t[c] = (c == p + 1) ? ip2 : t[c] * ip2;
                        #pragma unroll
                        for (int c = 0; c < NB; c++) sp[(p + 1) & 1][c] = t[c];
                    }
                }
            }
            // ---- batched dump of multipliers + pivots ----
            #pragma unroll
            for (int p = 0; p < NB; p++) Mul[p * U + r] = msave[p];
            if (r >= c0g && r < c0g + NB) g_ipiv[l][r] = ipreg;
            __threadfence();
            __syncthreads();
            if (r == 0) atomicExch(&g_flagw[l][kb], 1u);
        } else {
            if (r == 0) {
                while (atomicAdd(&g_flagw[l][kb], 0u) == 0u) { }
            }
            __syncthreads();
            float m[NB];
            #pragma unroll
            for (int p = 0; p < NB; p++) m[p] = Mul[p * U + r];
            if (r < NB) sipv[r] = g_ipiv[l][c0g + r];
            __syncthreads();
            if (r == c0g) {
                const float ip = sipv[0];
                #pragma unroll
                for (int c = 0; c < NB; c++) { t[c] *= ip; sp[0][c] = t[c]; }
            }
            #pragma unroll
            for (int p = 0; p < NB; p++) {
                __syncthreads();
                const int gp = c0g + p;
                if (r != gp) {
                    const float f = m[p];
                    #pragma unroll
                    for (int c = 0; c < NB; c += 4) {
                        float4 s4 = *(const float4*)&sp[p & 1][c];
                        t[c + 0] -= f * s4.x; t[c + 1] -= f * s4.y;
                        t[c + 2] -= f * s4.z; t[c + 3] -= f * s4.w;
                    }
                    if (p + 1 < NB && r == gp + 1) {
                        const float ip2 = sipv[p + 1];
                        #pragma unroll
                        for (int c = 0; c < NB; c++) { t[c] *= ip2; sp[(p + 1) & 1][c] = t[c]; }
                    }
                }
            }
        }
    }

    #pragma unroll
    for (int c = 0; c < NB; c += 4)
        *(float4*)&g_M[l][r * U + j0 + c] = *(float4*)&t[c];
}

// =====================================================================
// 64x64x256 GEMM tile, register double-buffered global loads.
// Per-element k-accumulation order identical to round 13.
//   mode 0: C = A*B   mode 1: C = 2I - A*B
//   mode 2: C = A*B, plus transposed-negated store to T
// =====================================================================
__device__ void gemm_tile(float* shbuf,
                          const float* __restrict__ A, const float* __restrict__ Bm,
                          float* __restrict__ C, float* __restrict__ T,
                          int mode, int bx, int by) {
    float (*As)[68] = (float(*)[68])shbuf;
    float (*Bs)[68] = (float(*)[68])(shbuf + 32 * 68);
    const int tid = threadIdx.x;
    const int i0 = by * 64, j0 = bx * 64;
    const int rf = (tid >> 4) * 4, cf = (tid & 15) * 4;

    // load-slot indices (slot0: s=tid, slot1: s=tid+256) — same as round 13
    const int iiA0 = tid >> 3,        kcA = (tid & 7) * 4;
    const int iiA1 = iiA0 + 32;
    const int kkB0 = tid >> 4,        jcB = (tid & 15) * 4;
    const int kkB1 = kkB0 + 16;

    float acc[4][4];
    #pragma unroll
    for (int r = 0; r < 4; r++)
        #pragma unroll
        for (int c = 0; c < 4; c++) acc[r][c] = 0.0f;

    float4 ra0, ra1, rb0, rb1;
    {
        ra0 = *(const float4*)&A[(i0 + iiA0) * U + kcA];
        ra1 = *(const float4*)&A[(i0 + iiA1) * U + kcA];
        rb0 = *(const float4*)&Bm[(kkB0) * U + j0 + jcB];
        rb1 = *(const float4*)&Bm[(kkB1) * U + j0 + jcB];
    }

    #pragma unroll 1
    for (int ch = 0; ch < 8; ch++) {
        // commit prefetched chunk to smem
        As[kcA + 0][iiA0] = ra0.x; As[kcA + 1][iiA0] = ra0.y;
        As[kcA + 2][iiA0] = ra0.z; As[kcA + 3][iiA0] = ra0.w;
        As[kcA + 0][iiA1] = ra1.x; As[kcA + 1][iiA1] = ra1.y;
        As[kcA + 2][iiA1] = ra1.z; As[kcA + 3][iiA1] = ra1.w;
        *(float4*)&Bs[kkB0][jcB] = rb0;
        *(float4*)&Bs[kkB1][jcB] = rb1;
        __syncthreads();
        if (ch < 7) {
            const int k0 = (ch + 1) * 32;
            ra0 = *(const float4*)&A[(i0 + iiA0) * U + k0 + kcA];
            ra1 = *(const float4*)&A[(i0 + iiA1) * U + k0 + kcA];
            rb0 = *(const float4*)&Bm[(k0 + kkB0) * U + j0 + jcB];
            rb1 = *(const float4*)&Bm[(k0 + kkB1) * U + j0 + jcB];
        }
        #pragma unroll
        for (int kk = 0; kk < 32; kk++) {
            float4 a4 = *(const float4*)&As[kk][rf];
            float4 b4 = *(const float4*)&Bs[kk][cf];
            float av[4] = {a4.x, a4.y, a4.z, a4.w};
            float bv[4] = {b4.x, b4.y, b4.z, b4.w};
            #pragma unroll
            for (int r = 0; r < 4; r++)
                #pragma unroll
                for (int c = 0; c < 4; c++) acc[r][c] += av[r] * bv[c];
        }
        __syncthreads();
    }
    if (mode == 2) {
        #pragma unroll
        for (int r = 0; r < 4; r++) {
            const int i = i0 + rf + r;
            *(float4*)&C[i * U + j0 + cf] =
                make_float4(acc[r][0], acc[r][1], acc[r][2], acc[r][3]);
        }
        #pragma unroll
        for (int c = 0; c < 4; c++) {
            const int j = j0 + cf + c;
            *(float4*)&T[j * U + i0 + rf] =
                make_float4(-acc[0][c], -acc[1][c], -acc[2][c], -acc[3][c]);
        }
    } else {
        #pragma unroll
        for (int r = 0; r < 4; r++) {
            int i = i0 + rf + r;
            #pragma unroll
            for (int c = 0; c < 4; c++) {
                int j = j0 + cf + c;
                float v = acc[r][c];
                if (mode == 1) v = ((i == j) ? 2.0f : 0.0f) - v;
                C[i * U + j] = v;
            }
        }
    }
}

// =====================================================================
// constant-chain layers [l0,l1): c0' = MTn_l*c1 ; c1' = M2_l*(c0+q_l)
// =====================================================================
__device__ void const_layers(int l0, int l1, const float* __restrict__ q,
                             float* c0s, float* c1s, float* rq) {
    const int n = threadIdx.x;
    for (int l = l0; l < l1; l++) {
        __syncthreads();
        rq[n] = c0s[n] + q[l * U + n];
        __syncthreads();
        const float* A0 = &g_MTn[l][0];
        const float* A1 = &g_M2[l][0];
        float acc0 = 0.0f, acc1 = 0.0f;
        for (int m = 0; m < U; m += 4) {
            float4 a4 = *(const float4*)&A0[n * U + m];
            acc0 += a4.x * c1s[m];     acc0 += a4.y * c1s[m + 1];
            acc0 += a4.z * c1s[m + 2]; acc0 += a4.w * c1s[m + 3];
            float4 b4 = *(const float4*)&A1[n * U + m];
            acc1 += b4.x * rq[m];      acc1 += b4.y * rq[m + 1];
            acc1 += b4.z * rq[m + 2];  acc1 += b4.w * rq[m + 3];
        }
        __syncthreads();
        c0s[n] = acc0; c1s[n] = acc1;
    }
}

// =====================================================================
// foldG / foldF (proven round-13)
// =====================================================================
__device__ void foldG_body(float* shbuf, const float* __restrict__ Wout,
                           const float* __restrict__ K, const float* __restrict__ c0,
                           const float* __restrict__ bin, const float* __restrict__ bout) {
    float* Ws = shbuf;
    float* Gs = shbuf + U * DOUT;
    const int m = threadIdx.x;
    for (int e = m; e < U * DOUT; e += 256) Ws[e] = Wout[e];
    __syncthreads();
    float acc[DOUT];
    #pragma unroll
    for (int d = 0; d < DOUT; d++) acc[d] = 0.0f;
    for (int n = 0; n < U; n++) {
        const float xv = K[n * U + m];
        #pragma unroll
        for (int d = 0; d < DOUT; d++) acc[d] += Ws[n * DOUT + d] * xv;
    }
    #pragma unroll
    for (int d = 0; d < DOUT; d++) { g_G[d * U + m] = acc[d]; Gs[d * U + m] = acc[d]; }
    __syncthreads();
    if (m < DOUT) {
        float f = bout[m];
        for (int e = 0; e < U; e++) f += Gs[m * U + e] * bin[e];
        for (int n = 0; n < U; n++) f += Ws[n * DOUT + m] * c0[n];
        g_f[m] = f;
    }
}

__device__ void foldF_body(float* shbuf, const float* __restrict__ Win, int blk) {
    float* Gs = shbuf;
    const int tid = threadIdx.x;
    for (int e = tid; e < DOUT * U; e += 256) Gs[e] = g_G[e];
    __syncthreads();
    const int k = blk * 256 + tid;
    if (k >= DIN) return;
    float acc[DOUT];
    #pragma unroll
    for (int d = 0; d < DOUT; d++) acc[d] = 0.0f;
    for (int m = 0; m < U; m++) {
        const float w = Win[(size_t)k * U + m];
        #pragma unroll
        for (int d = 0; d < DOUT; d++) acc[d] += Gs[d * U + m] * w;
    }
    #pragma unroll
    for (int d = 0; d < DOUT; d++) g_F[k * DOUT + d] = acc[d];
}

// =====================================================================
// mega kernel: setup phases in one launch (round-13 structure)
// =====================================================================
__global__ __launch_bounds__(256) void mega_kernel(const float* __restrict__ B0,
                                                   const float* __restrict__ q,
                                                   const float* __restrict__ Wout,
                                                   const float* __restrict__ bin,
                                                   const float* __restrict__ bout,
                                                   const float* __restrict__ Win) {
    __shared__ __align__(16) float shbuf[5376];
    __shared__ __align__(16) float sp[2][NB];
    __shared__ float sipv[NB];
    __shared__ float c0s[U], c1s[U], rq[U];
    const int cta = blockIdx.x;
    const int tid = threadIdx.x;

    // P0: reset inversion flags
    if (cta == 0 && tid < NL * NSTEP) ((unsigned int*)g_flagw)[tid] = 0u;
    grid_sync();

    // P1: flag-synced GENP inversion (48 CTAs)
    if (cta < 48) invert_body(B0, cta >> 3, cta & 7, sp, sipv);
    grid_sync();

    // P2: R = 2I - B0*M   (96 tiles)
    {
        const int l = cta >> 4, t = cta & 15;
        gemm_tile(shbuf, B0 + (size_t)l * SZ, g_M[l], g_R[l], nullptr, 1, t & 3, t >> 2);
    }
    grid_sync();

    // P3: M2 = M*R with fused MTn = -M2^T   (96 tiles)
    {
        const int l = cta >> 4, t = cta & 15;
        gemm_tile(shbuf, g_M[l], g_R[l], g_M2[l], g_MTn[l], 2, t & 3, t >> 2);
    }
    grid_sync();

    // P4: T_z = MTn[2z+1]*M2[2z] -> g_M[z]  (48 tiles);  CTA95: const 0-1
    if (cta < 48) {
        const int z = cta >> 4, t = cta & 15;
        gemm_tile(shbuf, g_MTn[2 * z + 1], g_M2[2 * z], g_M[z], nullptr, 0, t & 3, t >> 2);
    } else if (cta == NCTA - 1) {
        c0s[tid] = 0.0f; c1s[tid] = 0.0f;
        const_layers(0, 2, q, c0s, c1s, rq);
    }
    grid_sync();

    // P5: TT = T1*T0 -> g_M[3]  (16 tiles);  CTA95: const 2-3
    if (cta < 16) gemm_tile(shbuf, g_M[1], g_M[0], g_M[3], nullptr, 0, cta & 3, cta >> 2);
    else if (cta == NCTA - 1) const_layers(2, 4, q, c0s, c1s, rq);
    grid_sync();

    // P6: K = T2*TT -> g_M[4]  (16 tiles);  CTA95: const 4-5 + publish c0
    if (cta < 16) gemm_tile(shbuf, g_M[2], g_M[3], g_M[4], nullptr, 0, cta & 3, cta >> 2);
    else if (cta == NCTA - 1) {
        const_layers(4, 6, q, c0s, c1s, rq);
        g_c[tid] = c0s[tid];
    }
    grid_sync();

    // P7: foldG (CTA 0)
    if (cta == 0) foldG_body(shbuf, Wout, g_M[4], g_c, bin, bout);
    grid_sync();

    // P8: foldF (CTAs 0-3)
    if (cta < 4) foldF_body(shbuf, Win, cta);
}

// =====================================================================
// final: out[j][:] = F * x[j][:] + f  (proven round-13 kernel)
// =====================================================================
__global__ __launch_bounds__(128) void final_kernel(const float* __restrict__ x,
                                                    float* __restrict__ out) {
    __shared__ float Fs[DIN * DOUT];
    __shared__ float fsv[16];
    __shared__ __align__(16) float xs[4][16 * 33];
    const int tid = threadIdx.x;
    for (int e = tid; e < DIN * DOUT; e += 128) Fs[e] = g_F[e];
    if (tid < DOUT) fsv[tid] = g_f[tid];
    __syncthreads();

    const int w = tid >> 5, lane = tid & 31;
    const int row0 = blockIdx.x * 128 + w * 32;
    float* xw = xs[w];
    float acc[DOUT];
    #pragma unroll
    for (int d = 0; d < DOUT; d++) acc[d] = fsv[d];

    for (int k0 = 0; k0 < DIN; k0 += 16) {
        #pragma unroll
        for (int i = 0; i < 4; i++) {
            const int s = lane + 32 * i;
            const int r = s >> 2, kc = (s & 3) * 4;
            float4 v = *(const float4*)&x[(size_t)(row0 + r) * DIN + k0 + kc];
            xw[(kc + 0) * 33 + r] = v.x;
            xw[(kc + 1) * 33 + r] = v.y;
            xw[(kc + 2) * 33 + r] = v.z;
            xw[(kc + 3) * 33 + r] = v.w;
        }
        __syncwarp();
        #pragma unroll
        for (int kk = 0; kk < 16; kk++) {
            const float xv = xw[kk * 33 + lane];
            const float* Fp = &Fs[(k0 + kk) * DOUT];
            #pragma unroll
            for (int d = 0; d < DOUT; d++) acc[d] += xv * Fp[d];
        }
        __syncwarp();
    }
    const size_t j = (size_t)row0 + lane;
    #pragma unroll
    for (int d = 0; d < DOUT; d++) out[j * DOUT + d] = acc[d];
}

// =====================================================================
// launch  (2 launches total)
// =====================================================================
extern "C" void kernel_launch(void* const* d_in, const int* in_sizes, int n_in,
                              void* d_out, int out_size) {
    const float* x    = (const float*)d_in[0];
    const float* Win  = (const float*)d_in[1];
    const float* bin  = (const float*)d_in[2];
    const float* B0   = (const float*)d_in[3];
    const float* q    = (const float*)d_in[4];
    const float* Wout = (const float*)d_in[5];
    const float* bout = (const float*)d_in[6];
    float* out = (float*)d_out;

    mega_kernel<<<NCTA, 256>>>(B0, q, Wout, bin, bout, Win);
    final_kernel<<<BATCH / 128, 128>>>(x, out);
}

// round 17
// speedup vs baseline: 1.1492x; 1.0058x over previous
#include <cuda_runtime.h>
#include <math.h>
#include <stdint.h>

#define U     256
#define SZ    65536          // U*U
#define BATCH 32768
#define NL    6
#define DIN   784
#define DOUT  10
#define NB    32             // panel width
#define NSTEP (U / NB)       // 8 block steps
#define NSYNC 96             // setup CTAs participating in grid_sync
#define NCTAT 256            // total CTAs (96 setup + 160 workers)

// ===================== device-global scratch (no runtime allocs) =====================
__device__ float g_M   [NL][SZ];          // GENP inverse; later reused as tree bufs
__device__ float g_M2  [NL][SZ];          // Newton-refined inverse
__device__ float g_R   [NL][SZ];          // Newton residual
__device__ float g_MTn [NL][SZ];          // -(M2)^T
__device__ float g_Mul8[NSTEP][NL][NB * U]; // multipliers, per-step buffers, [p][r]
__device__ float g_ipiv[NL][U];           // 1/pivot per global step
__device__ unsigned int g_flagw[NL][NSTEP];
__device__ float g_c   [U];               // final constant c0
__device__ float g_G   [DOUT * U];
__device__ float g_F   [DIN * DOUT];
__device__ float g_f   [16];
__device__ float g_sink[NCTAT];           // prefetch DCE sink
__device__ unsigned int g_Fready = 0;     // F/f publication flag
__device__ unsigned int g_barcnt = 0;     // grid barrier state (setup CTAs only)
__device__ unsigned int g_bargen = 0;

// =====================================================================
// device-wide barrier among the NSYNC setup CTAs only
// =====================================================================
__device__ __forceinline__ void grid_sync() {
    __syncthreads();
    if (threadIdx.x == 0) {
        __threadfence();
        const unsigned int gen = atomicAdd(&g_bargen, 0u);
        if (atomicAdd(&g_barcnt, 1u) == NSYNC - 1) {
            g_barcnt = 0;
            __threadfence();
            atomicAdd(&g_bargen, 1u);
        } else {
            while (atomicAdd(&g_bargen, 0u) == gen) { }
        }
    }
    __syncthreads();
}

// =====================================================================
// inversion body (round-16: batched Mul/ipiv stores; proven arithmetic)
// =====================================================================
__device__ void invert_body(const float* __restrict__ B0, int l, int jt,
                            float (*sp)[NB], float* sipv) {
    const int r = threadIdx.x;
    const float* A = B0 + (size_t)l * SZ;
    const int j0 = jt * NB;

    float t[NB];
    #pragma unroll
    for (int c = 0; c < NB; c += 4)
        *(float4*)&t[c] = *(const float4*)&A[r * U + j0 + c];

    float msave[NB];
    float ipreg = 0.0f;

    #pragma unroll 1
    for (int kb = 0; kb < NSTEP; kb++) {
        float* Mul = &g_Mul8[kb][l][0];
        const int c0g = kb * NB;
        if (jt == kb) {
            if (r == c0g) {
                msave[0] = t[0];
                ipreg = 1.0f / t[0];
                #pragma unroll
                for (int c = 0; c < NB; c++) t[c] = (c == 0) ? ipreg : t[c] * ipreg;
                #pragma unroll
                for (int c = 0; c < NB; c++) sp[0][c] = t[c];
            }
            #pragma unroll
            for (int p = 0; p < NB; p++) {
                __syncthreads();
                const int gp = c0g + p;
                if (r != gp) {
                    const float f = t[p];
                    msave[p] = f;
                    const float ip = sp[p & 1][p];
                    #pragma unroll
                    for (int c = 0; c < NB; c += 4) {
                        float4 s4 = *(const float4*)&sp[p & 1][c];
                        t[c + 0] -= f * s4.x; t[c + 1] -= f * s4.y;
                        t[c + 2] -= f * s4.z; t[c + 3] -= f * s4.w;
                    }
                    t[p] = -f * ip;
                    if (p + 1 < NB && r == gp + 1) {
                        msave[p + 1] = t[p + 1];
                        const float ip2 = 1.0f / t[p + 1];
                        ipreg = ip2;
                        #pragma unroll
                        for (int c = 0; c < NB; c++)
                            t[c] = (c == p + 1) ? ip2 : t[c] * ip2;
                        #pragma unroll
                        for (int c = 0; c < NB; c++) sp[(p + 1) & 1][c] = t[c];
                    }
                }
            }
            #pragma unroll
            for (int p = 0; p < NB; p++) Mul[p * U + r] = msave[p];
            if (r >= c0g && r < c0g + NB) g_ipiv[l][r] = ipreg;
            __threadfence();
            __syncthreads();
            if (r == 0) atomicExch(&g_flagw[l][kb], 1u);
        } else {
            if (r == 0) {
                while (atomicAdd(&g_flagw[l][kb], 0u) == 0u) { }
            }
            __syncthreads();
            float m[NB];
            #pragma unroll
            for (int p = 0; p < NB; p++) m[p] = Mul[p * U + r];
            if (r < NB) sipv[r] = g_ipiv[l][c0g + r];
            __syncthreads();
            if (r == c0g) {
                const float ip = sipv[0];
                #pragma unroll
                for (int c = 0; c < NB; c++) { t[c] *= ip; sp[0][c] = t[c]; }
            }
            #pragma unroll
            for (int p = 0; p < NB; p++) {
                __syncthreads();
                const int gp = c0g + p;
                if (r != gp) {
                    const float f = m[p];
                    #pragma unroll
                    for (int c = 0; c < NB; c += 4) {
                        float4 s4 = *(const float4*)&sp[p & 1][c];
                        t[c + 0] -= f * s4.x; t[c + 1] -= f * s4.y;
                        t[c + 2] -= f * s4.z; t[c + 3] -= f * s4.w;
                    }
                    if (p + 1 < NB && r == gp + 1) {
                        const float ip2 = sipv[p + 1];
                        #pragma unroll
                        for (int c = 0; c < NB; c++) { t[c] *= ip2; sp[(p + 1) & 1][c] = t[c]; }
                    }
                }
            }
        }
    }

    #pragma unroll
    for (int c = 0; c < NB; c += 4)
        *(float4*)&g_M[l][r * U + j0 + c] = *(float4*)&t[c];
}

// =====================================================================
// 64x64x256 GEMM tile, register double-buffered (round-16, proven)
// =====================================================================
__device__ void gemm_tile(float* shbuf,
                          const float* __restrict__ A, const float* __restrict__ Bm,
                          float* __restrict__ C, float* __restrict__ T,
                          int mode, int bx, int by) {
    float (*As)[68] = (float(*)[68])shbuf;
    float (*Bs)[68] = (float(*)[68])(shbuf + 32 * 68);
    const int tid = threadIdx.x;
    const int i0 = by * 64, j0 = bx * 64;
    const int rf = (tid >> 4) * 4, cf = (tid & 15) * 4;

    const int iiA0 = tid >> 3,        kcA = (tid & 7) * 4;
    const int iiA1 = iiA0 + 32;
    const int kkB0 = tid >> 4,        jcB = (tid & 15) * 4;
    const int kkB1 = kkB0 + 16;

    float acc[4][4];
    #pragma unroll
    for (int r = 0; r < 4; r++)
        #pragma unroll
        for (int c = 0; c < 4; c++) acc[r][c] = 0.0f;

    float4 ra0, ra1, rb0, rb1;
    ra0 = *(const float4*)&A[(i0 + iiA0) * U + kcA];
    ra1 = *(const float4*)&A[(i0 + iiA1) * U + kcA];
    rb0 = *(const float4*)&Bm[(kkB0) * U + j0 + jcB];
    rb1 = *(const float4*)&Bm[(kkB1) * U + j0 + jcB];

    #pragma unroll 1
    for (int ch = 0; ch < 8; ch++) {
        As[kcA + 0][iiA0] = ra0.x; As[kcA + 1][iiA0] = ra0.y;
        As[kcA + 2][iiA0] = ra0.z; As[kcA + 3][iiA0] = ra0.w;
        As[kcA + 0][iiA1] = ra1.x; As[kcA + 1][iiA1] = ra1.y;
        As[kcA + 2][iiA1] = ra1.z; As[kcA + 3][iiA1] = ra1.w;
        *(float4*)&Bs[kkB0][jcB] = rb0;
        *(float4*)&Bs[kkB1][jcB] = rb1;
        __syncthreads();
        if (ch < 7) {
            const int k0 = (ch + 1) * 32;
            ra0 = *(const float4*)&A[(i0 + iiA0) * U + k0 + kcA];
            ra1 = *(const float4*)&A[(i0 + iiA1) * U + k0 + kcA];
            rb0 = *(const float4*)&Bm[(k0 + kkB0) * U + j0 + jcB];
            rb1 = *(const float4*)&Bm[(k0 + kkB1) * U + j0 + jcB];
        }
        #pragma unroll
        for (int kk = 0; kk < 32; kk++) {
            float4 a4 = *(const float4*)&As[kk][rf];
            float4 b4 = *(const float4*)&Bs[kk][cf];
            float av[4] = {a4.x, a4.y, a4.z, a4.w};
            float bv[4] = {b4.x, b4.y, b4.z, b4.w};
            #pragma unroll
            for (int r = 0; r < 4; r++)
                #pragma unroll
                for (int c = 0; c < 4; c++) acc[r][c] += av[r] * bv[c];
        }
        __syncthreads();
    }
    if (mode == 2) {
        #pragma unroll
        for (int r = 0; r < 4; r++) {
            const int i = i0 + rf + r;
            *(float4*)&C[i * U + j0 + cf] =
                make_float4(acc[r][0], acc[r][1], acc[r][2], acc[r][3]);
        }
        #pragma unroll
        for (int c = 0; c < 4; c++) {
            const int j = j0 + cf + c;
            *(float4*)&T[j * U + i0 + rf] =
                make_float4(-acc[0][c], -acc[1][c], -acc[2][c], -acc[3][c]);
        }
    } else {
        #pragma unroll
        for (int r = 0; r < 4; r++) {
            int i = i0 + rf + r;
            #pragma unroll
            for (int c = 0; c < 4; c++) {
                int j = j0 + cf + c;
                float v = acc[r][c];
                if (mode == 1) v = ((i == j) ? 2.0f : 0.0f) - v;
                C[i * U + j] = v;
            }
        }
    }
}

// =====================================================================
// constant-chain layers (proven)
// =====================================================================
__device__ void const_layers(int l0, int l1, const float* __restrict__ q,
                             float* c0s, float* c1s, float* rq) {
    const int n = threadIdx.x;
    for (int l = l0; l < l1; l++) {
        __syncthreads();
        rq[n] = c0s[n] + q[l * U + n];
        __syncthreads();
        const float* A0 = &g_MTn[l][0];
        const float* A1 = &g_M2[l][0];
        float acc0 = 0.0f, acc1 = 0.0f;
        for (int m = 0; m < U; m += 4) {
            float4 a4 = *(const float4*)&A0[n * U + m];
            acc0 += a4.x * c1s[m];     acc0 += a4.y * c1s[m + 1];
            acc0 += a4.z * c1s[m + 2]; acc0 += a4.w * c1s[m + 3];
            float4 b4 = *(const float4*)&A1[n * U + m];
            acc1 += b4.x * rq[m];      acc1 += b4.y * rq[m + 1];
            acc1 += b4.z * rq[m + 2];  acc1 += b4.w * rq[m + 3];
        }
        __syncthreads();
        c0s[n] = acc0; c1s[n] = acc1;
    }
}

// =====================================================================
// foldG / foldF (proven)
// =====================================================================
__device__ void foldG_body(float* shbuf, const float* __restrict__ Wout,
                           const float* __restrict__ K, const float* __restrict__ c0,
                           const float* __restrict__ bin, const float* __restrict__ bout) {
    float* Ws = shbuf;
    float* Gs = shbuf + U * DOUT;
    const int m = threadIdx.x;
    for (int e = m; e < U * DOUT; e += 256) Ws[e] = Wout[e];
    __syncthreads();
    float acc[DOUT];
    #pragma unroll
    for (int d = 0; d < DOUT; d++) acc[d] = 0.0f;
    for (int n = 0; n < U; n++) {
        const float xv = K[n * U + m];
        #pragma unroll
        for (int d = 0; d < DOUT; d++) acc[d] += Ws[n * DOUT + d] * xv;
    }
    #pragma unroll
    for (int d = 0; d < DOUT; d++) { g_G[d * U + m] = acc[d]; Gs[d * U + m] = acc[d]; }
    __syncthreads();
    if (m < DOUT) {
        float f = bout[m];
        for (int e = 0; e < U; e++) f += Gs[m * U + e] * bin[e];
        for (int n = 0; n < U; n++) f += Ws[n * DOUT + m] * c0[n];
        g_f[m] = f;
    }
}

__device__ void foldF_body(float* shbuf, const float* __restrict__ Win, int blk) {
    float* Gs = shbuf;
    const int tid = threadIdx.x;
    for (int e = tid; e < DOUT * U; e += 256) Gs[e] = g_G[e];
    __syncthreads();
    const int k = blk * 256 + tid;
    if (k >= DIN) return;
    float acc[DOUT];
    #pragma unroll
    for (int d = 0; d < DOUT; d++) acc[d] = 0.0f;
    for (int m = 0; m < U; m++) {
        const float w = Win[(size_t)k * U + m];
        #pragma unroll
        for (int d = 0; d < DOUT; d++) acc[d] += Gs[d * U + m] * w;
    }
    #pragma unroll
    for (int d = 0; d < DOUT; d++) g_F[k * DOUT + d] = acc[d];
}

// =====================================================================
// x prefetch into L2 (workers, overlapped with ALL setup phases)
// =====================================================================
__device__ void prefetch_x(const float* __restrict__ x, int slot) {
    const size_t total4 = (size_t)BATCH * DIN / 4;
    const size_t stride = (size_t)(NCTAT - NSYNC) * 256;
    float acc = 0.0f;
    for (size_t i = (size_t)slot * 256 + threadIdx.x; i < total4; i += stride) {
        float4 v = ((const float4*)x)[i];
        acc += v.x + v.y + v.z + v.w;
    }
    #pragma unroll
    for (int o = 16; o > 0; o >>= 1)
        acc += __shfl_down_sync(0xFFFFFFFFu, acc, o);
    if ((threadIdx.x & 31) == 0) g_sink[blockIdx.x] = acc;
}

// =====================================================================
// final pass: 128 rows per CTA, one row per thread (tid<128), x L2-hot.
// k-ascending accumulation, identical order to the proven final kernel.
// =====================================================================
__device__ void final_rows(float* Fs, float* fsv,
                           const float* __restrict__ x, float* __restrict__ out) {
    const int tid = threadIdx.x;
    for (int e = tid; e < DIN * DOUT; e += 256) {
        const int k = e / DOUT, d = e - k * DOUT;
        Fs[k * 12 + d] = g_F[e];
    }
    if (tid < DOUT) fsv[tid] = g_f[tid];
    __syncthreads();

    if (tid >= 128) return;
    const int j = (int)blockIdx.x * 128 + tid;
    const float* xr = x + (size_t)j * DIN;
    float acc[DOUT];
    #pragma unroll
    for (int d = 0; d < DOUT; d++) acc[d] = fsv[d];

    #pragma unroll 1
    for (int k = 0; k < DIN; k += 16) {
        float4 xv4[4];
        xv4[0] = *(const float4*)&xr[k];
        xv4[1] = *(const float4*)&xr[k + 4];
        xv4[2] = *(const float4*)&xr[k + 8];
        xv4[3] = *(const float4*)&xr[k + 12];
        const float* xk = (const float*)xv4;
        #pragma unroll
        for (int kk = 0; kk < 16; kk++) {
            const float xv = xk[kk];
            const float* Fp = &Fs[(k + kk) * 12];
            float4 f0 = *(const float4*)&Fp[0];
            float4 f1 = *(const float4*)&Fp[4];
            float2 f2 = *(const float2*)&Fp[8];
            acc[0] += xv * f0.x; acc[1] += xv * f0.y;
            acc[2] += xv * f0.z; acc[3] += xv * f0.w;
            acc[4] += xv * f1.x; acc[5] += xv * f1.y;
            acc[6] += xv * f1.z; acc[7] += xv * f1.w;
            acc[8] += xv * f2.x; acc[9] += xv * f2.y;
        }
    }
    #pragma unroll
    for (int d = 0; d < DOUT; d++) out[(size_t)j * DOUT + d] = acc[d];
}

// =====================================================================
// THE mega kernel: setup (96 sync'd CTAs) + workers (160 prefetch/final)
// =====================================================================
__global__ __launch_bounds__(256, 2) void mega_kernel(const float* __restrict__ B0,
                                                      const float* __restrict__ q,
                                                      const float* __restrict__ Wout,
                                                      const float* __restrict__ bin,
                                                      const float* __restrict__ bout,
                                                      const float* __restrict__ Win,
                                                      const float* __restrict__ x,
                                                      float* __restrict__ out) {
    __shared__ __align__(16) float shbuf[9420];   // gemm/folds/Fs(stride12)
    __shared__ __align__(16) float sp[2][NB];
    __shared__ float sipv[NB];
    __shared__ float c0s[U], c1s[U], rq[U];
    __shared__ float fsv[16];
    const int cta = blockIdx.x;
    const int tid = threadIdx.x;

    // ---------------- worker path (no grid_sync participation) ----------------
    if (cta >= NSYNC) {
        prefetch_x(x, cta - NSYNC);
        if (tid == 0) {
            while (atomicAdd(&g_Fready, 0u) == 0u) { }
        }
        __syncthreads();
        final_rows(shbuf, fsv, x, out);
        return;
    }

    // ---------------- setup path ----------------
    // P0: reset inversion flags
    if (cta == 0 && tid < NL * NSTEP) ((unsigned int*)g_flagw)[tid] = 0u;
    grid_sync();

    // P1: flag-synced GENP inversion (48 CTAs)
    if (cta < 48) invert_body(B0, cta >> 3, cta & 7, sp, sipv);
    grid_sync();

    // P2: R = 2I - B0*M   (96 tiles)
    {
        const int l = cta >> 4, t = cta & 15;
        gemm_tile(shbuf, B0 + (size_t)l * SZ, g_M[l], g_R[l], nullptr, 1, t & 3, t >> 2);
    }
    grid_sync();

    // P3: M2 = M*R with fused MTn = -M2^T   (96 tiles)
    {
        const int l = cta >> 4, t = cta & 15;
        gemm_tile(shbuf, g_M[l], g_R[l], g_M2[l], g_MTn[l], 2, t & 3, t >> 2);
    }
    grid_sync();

    // P4: T_z = MTn[2z+1]*M2[2z] -> g_M[z]  (48 tiles);  CTA95: const 0-1
    if (cta < 48) {
        const int z = cta >> 4, t = cta & 15;
        gemm_tile(shbuf, g_MTn[2 * z + 1], g_M2[2 * z], g_M[z], nullptr, 0, t & 3, t >> 2);
    } else if (cta == NSYNC - 1) {
        c0s[tid] = 0.0f; c1s[tid] = 0.0f;
        const_layers(0, 2, q, c0s, c1s, rq);
    }
    grid_sync();

    // P5: TT = T1*T0 -> g_M[3]  (16 tiles);  CTA95: const 2-3
    if (cta < 16) gemm_tile(shbuf, g_M[1], g_M[0], g_M[3], nullptr, 0, cta & 3, cta >> 2);
    else if (cta == NSYNC - 1) const_layers(2, 4, q, c0s, c1s, rq);
    grid_sync();

    // P6: K = T2*TT -> g_M[4]  (16 tiles);  CTA95: const 4-5 + publish c0
    if (cta < 16) gemm_tile(shbuf, g_M[2], g_M[3], g_M[4], nullptr, 0, cta & 3, cta >> 2);
    else if (cta == NSYNC - 1) {
        const_layers(4, 6, q, c0s, c1s, rq);
        g_c[tid] = c0s[tid];
    }
    grid_sync();

    // P7: foldG (CTA 0)
    if (cta == 0) foldG_body(shbuf, Wout, g_M[4], g_c, bin, bout);
    grid_sync();

    // P8: foldF (CTAs 0-3)
    if (cta < 4) foldF_body(shbuf, Win, cta);
    grid_sync();

    // publish F-ready for workers
    if (cta == 0 && tid == 0) {
        __threadfence();
        atomicExch(&g_Fready, 1u);
    }

    // P9: setup CTAs handle their 128-row slices too
    final_rows(shbuf, fsv, x, out);
}

// =====================================================================
// launch  (1 launch total)
// =====================================================================
extern "C" void kernel_launch(void* const* d_in, const int* in_sizes, int n_in,
                              void* d_out, int out_size) {
    const float* x    = (const float*)d_in[0];
    const float* Win  = (const float*)d_in[1];
    const float* bin  = (const float*)d_in[2];
    const float* B0   = (const float*)d_in[3];
    const float* q    = (const float*)d_in[4];
    const float* Wout = (const float*)d_in[5];
    const float* bout = (const float*)d_in[6];
    float* out = (float*)d_out;

    mega_kernel<<<NCTAT, 256>>>(B0, q, Wout, bin, bout, Win, x, out);
}